// round 8
// baseline (speedup 1.0000x reference)
#include <cuda_runtime.h>
#include <cstdint>

// Problem shape (fixed by the dataset):
//   features:        (BS=4, C=64, P=12000) float32
//   x_orig_indices:  (BS, P) int32  (JAX x64 disabled: "int64" is silently int32)
//   y_orig_indices:  (BS, P) int32
//   output pseudo:   (BS, C, NY=440, NX=500) float32
#define BS     4
#define CCH    64
#define NP     12000
#define NXP    500
#define NYP    440
#define CELLS  (NXP * NYP)            // 220000
#define CHUNK  2048                   // cells per block tile (8KB fp32)
#define NCHUNK ((CELLS + CHUNK - 1) / CHUNK)  // 108 (last chunk = 864 cells)
#define NBUF   4                      // TMA pipeline depth

// Scratch (allocation-free device globals).
// g_winner: int32, (winning p)+1 or 0. Zero at module load; pack_kernel resets
//           it every launch after reading (sole reader) -> replay-safe.
// g_w16:    uint16 compressed winner used by the gather.
__device__ int            g_winner[BS * CELLS];
__device__ unsigned short g_w16[BS * CELLS];

__device__ __forceinline__ uint32_t smem_u32(const void* p) {
    uint32_t a;
    asm("{ .reg .u64 t; cvta.to.shared.u64 t, %1; cvt.u32.u64 %0, t; }"
        : "=r"(a) : "l"(p));
    return a;
}

// ---------------------------------------------------------------------------
// Phase 1: winner pass — JAX sequential .set semantics == last p wins == max p.
// ---------------------------------------------------------------------------
__global__ void winner_kernel(const int* __restrict__ xi,
                              const int* __restrict__ yi) {
    int i = blockIdx.x * blockDim.x + threadIdx.x;
    if (i >= BS * NP) return;
    int b = i / NP;
    int p = i - b * NP;

    int x = xi[i];
    int y = yi[i];
    // jnp.clip semantics
    x = x < 0 ? 0 : (x >= NXP ? NXP - 1 : x);
    y = y < 0 ? 0 : (y >= NYP ? NYP - 1 : y);
    int cell = y * NXP + x;

    atomicMax(&g_winner[b * CELLS + cell], p + 1);
}

// ---------------------------------------------------------------------------
// Phase 2: pack int32 winner -> uint16, reset int32 winner for next launch.
// ---------------------------------------------------------------------------
__global__ void pack_kernel() {
    const int n4 = (BS * CELLS) / 4;   // 220000
    int i = blockIdx.x * blockDim.x + threadIdx.x;
    if (i >= n4) return;

    int4* wp = reinterpret_cast<int4*>(g_winner) + i;
    int4 w = *wp;
    *wp = make_int4(0, 0, 0, 0);       // reset for next replay

    ushort4 s;
    s.x = (unsigned short)w.x;
    s.y = (unsigned short)w.y;
    s.z = (unsigned short)w.z;
    s.w = (unsigned short)w.w;
    reinterpret_cast<ushort4*>(g_w16)[i] = s;
}

// ---------------------------------------------------------------------------
// Phase 3: TMA-store gather. Block = one 2048-cell chunk of one batch.
//  - winner u16 read ONCE per chunk (3.5MB total winner traffic).
//  - compact (cell,p) list built in smem (~5.3% occupancy -> ~108 entries).
//  - 4 smem buffers zeroed once; per channel only list cells are overwritten,
//    then one 8KB cp.async.bulk shared->global streams the tile out.
//    Writes leave as monolithic contiguous bursts -> memset-class DRAM
//    efficiency, no L1 store path, ~10 instructions per 8KB.
// ---------------------------------------------------------------------------
__global__ void __launch_bounds__(256, 1)
tma_gather_kernel(const float* __restrict__ feat,
                  float* __restrict__ out) {
    __shared__ float        buf[NBUF][CHUNK];  // 32KB
    __shared__ unsigned int list[CHUNK];       // 8KB (cell<<16 | p+1)
    __shared__ int          cnt;

    const int tid   = threadIdx.x;
    const int chunk = blockIdx.x;
    const int b     = blockIdx.y;
    const int base  = chunk * CHUNK;
    const int ncell = min(CHUNK, CELLS - base);
    const int nbytes = ncell * 4;              // multiple of 16 (864*4=3456)

    if (tid == 0) cnt = 0;
    // Zero all buffers once (non-list cells stay zero for all 64 channels).
    {
        float4* bz = reinterpret_cast<float4*>(&buf[0][0]);
        #pragma unroll
        for (int k = 0; k < (NBUF * CHUNK / 4) / 256; k++)   // 8 iters
            bz[tid + k * 256] = make_float4(0.f, 0.f, 0.f, 0.f);
    }
    __syncthreads();

    // Build compact winner list: 8 cells per thread, one uint4 (16B) read.
    {
        const unsigned short* wrow = g_w16 + b * CELLS + base;
        int c0 = tid * 8;
        if (c0 < ncell) {
            uint4 w = *reinterpret_cast<const uint4*>(wrow + c0);
            unsigned int parts[4] = {w.x, w.y, w.z, w.w};
            #pragma unroll
            for (int j = 0; j < 8; j++) {
                unsigned int p = (parts[j >> 1] >> ((j & 1) * 16)) & 0xFFFFu;
                if (p && (c0 + j) < ncell) {
                    int pos = atomicAdd(&cnt, 1);
                    list[pos] = ((unsigned int)(c0 + j) << 16) | p;
                }
            }
        }
    }
    __syncthreads();
    const int n = cnt;

    const float* fbase = feat + (size_t)b * CCH * NP;
    float*       obase = out + (size_t)b * CCH * CELLS + base;
    uint32_t sbuf[NBUF];
    #pragma unroll
    for (int k = 0; k < NBUF; k++) sbuf[k] = smem_u32(&buf[k][0]);

    for (int c = 0; c < CCH; c++) {
        const int bi = c & (NBUF - 1);
        // Ensure the store issued NBUF iterations ago (same buffer) is done.
        if (tid == 0)
            asm volatile("cp.async.bulk.wait_group %0;" :: "n"(NBUF - 1) : "memory");
        __syncthreads();

        // Overwrite only the winner cells with this channel's values.
        const float* frow = fbase + (size_t)c * NP;
        for (int e = tid; e < n; e += 256) {
            unsigned int ent = list[e];
            buf[bi][ent >> 16] = __ldg(frow + (ent & 0xFFFFu) - 1);
        }
        __syncthreads();

        if (tid == 0) {
            asm volatile("fence.proxy.async.shared::cta;" ::: "memory");
            asm volatile(
                "cp.async.bulk.global.shared::cta.bulk_group [%0], [%1], %2;"
                :: "l"(obase + (size_t)c * CELLS), "r"(sbuf[bi]), "r"(nbytes)
                : "memory");
            asm volatile("cp.async.bulk.commit_group;" ::: "memory");
        }
    }

    // Drain all outstanding bulk stores before smem is released.
    if (tid == 0)
        asm volatile("cp.async.bulk.wait_group 0;" ::: "memory");
    __syncthreads();
}

// ---------------------------------------------------------------------------
extern "C" void kernel_launch(void* const* d_in, const int* in_sizes, int n_in,
                              void* d_out, int out_size) {
    const float* feat = (const float*)d_in[0];
    const int*   xi   = (const int*)d_in[1];
    const int*   yi   = (const int*)d_in[2];
    float* out = (float*)d_out;

    {   // winner pass
        int n = BS * NP;
        int threads = 256;
        int blocks = (n + threads - 1) / threads;
        winner_kernel<<<blocks, threads>>>(xi, yi);
    }
    {   // pack to u16 + reset
        const int n4 = (BS * CELLS) / 4;
        int threads = 256;
        int blocks = (n4 + threads - 1) / threads;
        pack_kernel<<<blocks, threads>>>();
    }
    {   // TMA-store gather (writes every output element)
        dim3 grid(NCHUNK, BS);       // (108, 4) = 432 blocks
        tma_gather_kernel<<<grid, 256>>>(feat, out);
    }
}

// round 9
// speedup vs baseline: 1.4403x; 1.4403x over previous
#include <cuda_runtime.h>
#include <cstdint>

// Problem shape (fixed by the dataset):
//   features:        (BS=4, C=64, P=12000) float32
//   x_orig_indices:  (BS, P) int32  (JAX x64 disabled: "int64" is silently int32)
//   y_orig_indices:  (BS, P) int32
//   output pseudo:   (BS, C, NY=440, NX=500) float32
#define BS     4
#define CCH    64
#define NP     12000
#define NXP    500
#define NYP    440
#define CELLS  (NXP * NYP)          // 220000
#define CELLS8 (CELLS / 8)          // 27500 cell8-groups per batch
#define NWORDS ((CELLS8 + 31) / 32) // 860 bitmap words per batch
#define NOUT   (BS * CCH * CELLS)   // 56,320,000

// Scratch (allocation-free device globals).
// g_winner: int32, (winning p)+1 or 0. Zeroed at module load; pack_kernel
//           resets it after reading (sole reader) -> replay-safe.
// g_w16:    u16 compressed winner, read only by slow-path gather threads.
// g_bitmap: 1 bit per cell8 group ("any winner here?"), 13.8KB total,
//           L1-resident; zeroed by winner_kernel each launch, set by pack.
__device__ int            g_winner[BS * CELLS];
__device__ unsigned short g_w16[BS * CELLS];
__device__ unsigned int   g_bitmap[BS * NWORDS];

// ---------------------------------------------------------------------------
// Phase 1: winner pass — JAX sequential .set semantics == last p wins == max p.
// Also zeroes the bitmap for this launch (ordered before pack's atomicOr by
// the kernel boundary).
// ---------------------------------------------------------------------------
__global__ void winner_kernel(const int* __restrict__ xi,
                              const int* __restrict__ yi) {
    int i = blockIdx.x * blockDim.x + threadIdx.x;
    if (i < BS * NWORDS) g_bitmap[i] = 0u;
    if (i >= BS * NP) return;
    int b = i / NP;
    int p = i - b * NP;

    int x = xi[i];
    int y = yi[i];
    // jnp.clip semantics
    x = x < 0 ? 0 : (x >= NXP ? NXP - 1 : x);
    y = y < 0 ? 0 : (y >= NYP ? NYP - 1 : y);
    int cell = y * NXP + x;

    atomicMax(&g_winner[b * CELLS + cell], p + 1);
}

// ---------------------------------------------------------------------------
// Phase 2: pack int32 winner -> u16 (+ bitmap bit per cell8 group), and reset
// the int32 winner for the next launch. One thread per 8 cells.
// ---------------------------------------------------------------------------
__global__ void pack_kernel() {
    const int n8 = BS * CELLS8;        // 110000
    int i = blockIdx.x * blockDim.x + threadIdx.x;
    if (i >= n8) return;
    int b      = i / CELLS8;
    int group  = i - b * CELLS8;       // cell8 index within batch

    int4* wp = reinterpret_cast<int4*>(g_winner + b * CELLS) + group * 2;
    int4 w0 = wp[0];
    int4 w1 = wp[1];
    wp[0] = make_int4(0, 0, 0, 0);     // reset for next replay
    wp[1] = make_int4(0, 0, 0, 0);

    uint4 s;
    s.x = (unsigned int)(w0.x & 0xFFFF) | ((unsigned int)w0.y << 16);
    s.y = (unsigned int)(w0.z & 0xFFFF) | ((unsigned int)w0.w << 16);
    s.z = (unsigned int)(w1.x & 0xFFFF) | ((unsigned int)w1.y << 16);
    s.w = (unsigned int)(w1.z & 0xFFFF) | ((unsigned int)w1.w << 16);
    reinterpret_cast<uint4*>(g_w16 + b * CELLS)[group] = s;

    if (s.x | s.y | s.z | s.w)
        atomicOr(&g_bitmap[b * NWORDS + (group >> 5)], 1u << (group & 31));
}

// ---------------------------------------------------------------------------
// Phase 3: fused zero-fill + gather, linear-sweep layout (proven best DRAM
// pattern). 2D grid: x = cell8 within plane (no divisions), y = plane (b,c).
// Fast path (~73%): one L1-broadcast 4B bitmap load (one word per warp),
// then two dependency-free streaming zero-stores -> memset-class stream.
// Slow path (~27%): 16B w16 load + predicated feature gathers.
// ---------------------------------------------------------------------------
__global__ void gather_kernel(const float* __restrict__ feat,
                              float* __restrict__ out) {
    const int group = blockIdx.x * blockDim.x + threadIdx.x;  // cell8 in plane
    if (group >= CELLS8) return;
    const int bc = blockIdx.y;                                // b*CCH + c
    const int b  = bc >> 6;

    // One word covers 32 groups == exactly one warp -> broadcast load.
    unsigned int word = __ldg(&g_bitmap[b * NWORDS + (group >> 5)]);

    float4* o = reinterpret_cast<float4*>(out + (size_t)bc * CELLS) + group * 2;

    if (!((word >> (group & 31)) & 1u)) {
        const float4 z = make_float4(0.f, 0.f, 0.f, 0.f);
        __stcs(o,     z);
        __stcs(o + 1, z);
    } else {
        uint4 w = __ldg(reinterpret_cast<const uint4*>(g_w16 + b * CELLS) + group);
        const float* frow = feat + (size_t)bc * NP;   // 48KB row, L1/L2-hot
        int p0 = (int)(w.x & 0xFFFFu), p1 = (int)(w.x >> 16);
        int p2 = (int)(w.y & 0xFFFFu), p3 = (int)(w.y >> 16);
        int p4 = (int)(w.z & 0xFFFFu), p5 = (int)(w.z >> 16);
        int p6 = (int)(w.w & 0xFFFFu), p7 = (int)(w.w >> 16);
        float4 v0, v1;
        v0.x = p0 ? __ldg(frow + p0 - 1) : 0.f;
        v0.y = p1 ? __ldg(frow + p1 - 1) : 0.f;
        v0.z = p2 ? __ldg(frow + p2 - 1) : 0.f;
        v0.w = p3 ? __ldg(frow + p3 - 1) : 0.f;
        v1.x = p4 ? __ldg(frow + p4 - 1) : 0.f;
        v1.y = p5 ? __ldg(frow + p5 - 1) : 0.f;
        v1.z = p6 ? __ldg(frow + p6 - 1) : 0.f;
        v1.w = p7 ? __ldg(frow + p7 - 1) : 0.f;
        __stcs(o,     v0);
        __stcs(o + 1, v1);
    }
}

// ---------------------------------------------------------------------------
extern "C" void kernel_launch(void* const* d_in, const int* in_sizes, int n_in,
                              void* d_out, int out_size) {
    const float* feat = (const float*)d_in[0];
    const int*   xi   = (const int*)d_in[1];
    const int*   yi   = (const int*)d_in[2];
    float* out = (float*)d_out;

    {   // winner pass (+ bitmap zeroing)
        int n = BS * NP;
        int threads = 256;
        int blocks = (n + threads - 1) / threads;
        winner_kernel<<<blocks, threads>>>(xi, yi);
    }
    {   // pack to u16 + bitmap + reset
        int n = BS * CELLS8;
        int threads = 256;
        int blocks = (n + threads - 1) / threads;
        pack_kernel<<<blocks, threads>>>();
    }
    {   // fused zero + gather (writes every output element)
        dim3 grid((CELLS8 + 255) / 256, BS * CCH);   // (108, 256)
        gather_kernel<<<grid, 256>>>(feat, out);
    }
}